// round 9
// baseline (speedup 1.0000x reference)
#include <cuda_runtime.h>
#include <math.h>

#define GN 256
#define NVOX (GN*GN*GN)          // 2^24
#define MAX_ID 32
#define NUM_CLASSES 13
#define NBINS ((MAX_ID+1)*NUM_CLASSES)   // 429
#define LUT_SZ (MAX_ID+3)                // 35

// ---------------- device scratch (no allocations allowed) ----------------
__device__ int           g_counts[NBINS];
__device__ int           g_pano_lut[MAX_ID+1];
__device__ int           g_sem_lut[LUT_SZ];
__device__ unsigned char g_grid0[NVOX];

__device__ const float* g_geo;
__device__ const int*   g_inst;
__device__ const int*   g_sem;

// ---------------- kernel A: classify big buffers by content (3 warps) ----------------
// semantics in [0,13): sampled max < 13
// instances in [0,32): sampled max in [13,32)
// geometry  = float bits: max int-interpretation > 1e6 or negative
__global__ void classifyK(const int* a, const int* b, const int* c) {
    __shared__ int smax[3];
    const int* bufs[3] = { a, b, c };
    int w = threadIdx.x >> 5, lane = threadIdx.x & 31;
    if (w < 3) {
        const int* p = bufs[w];
        int mx = -2147483647;
        for (int i = lane; i < 2048; i += 32) {
            int v = p[i * 769];               // 2048*769 < 2^24, strided sample
            mx = v > mx ? v : mx;
        }
        for (int o = 16; o > 0; o >>= 1) {
            int t = __shfl_xor_sync(0xFFFFFFFFu, mx, o);
            mx = t > mx ? t : mx;
        }
        if (lane == 0) smax[w] = mx;
    }
    __syncthreads();
    if (threadIdx.x == 0) {
        bool used[3] = { false, false, false };
        bool gs = false, ss = false, is = false;
        for (int t = 0; t < 3; t++)
            if (!used[t] && (smax[t] > 1000000 || smax[t] < 0)) {
                g_geo = (const float*)bufs[t]; used[t] = true; gs = true; break;
            }
        for (int t = 0; t < 3; t++)
            if (!used[t] && smax[t] < 13) {
                g_sem = bufs[t]; used[t] = true; ss = true; break;
            }
        for (int t = 0; t < 3; t++)
            if (!used[t]) { g_inst = bufs[t]; used[t] = true; is = true; break; }
        if (!gs) g_geo  = (const float*)a;   // positional fallback (never expected)
        if (!ss) g_sem  = c;
        if (!is) g_inst = b;
    }
    // zero histogram
    for (int i = threadIdx.x; i < NBINS; i += blockDim.x) g_counts[i] = 0;
}

// ---------------- kernel 1: joint (instance, semantic) histogram ----------------
__global__ void histK() {
    __shared__ int sc[NBINS];
    for (int i = threadIdx.x; i < NBINS; i += blockDim.x) sc[i] = 0;
    __syncthreads();
    const int4* inst4 = (const int4*)g_inst;
    const int4* sem4  = (const int4*)g_sem;
    int stride = gridDim.x * blockDim.x;
    int n4 = NVOX / 4;
    for (int i = blockIdx.x * blockDim.x + threadIdx.x; i < n4; i += stride) {
        int4 v = inst4[i];
        int4 s = sem4[i];
        unsigned ix;
        ix = (unsigned)(v.x * NUM_CLASSES + s.x); if (ix < NBINS) atomicAdd(&sc[ix], 1);
        ix = (unsigned)(v.y * NUM_CLASSES + s.y); if (ix < NBINS) atomicAdd(&sc[ix], 1);
        ix = (unsigned)(v.z * NUM_CLASSES + s.z); if (ix < NBINS) atomicAdd(&sc[ix], 1);
        ix = (unsigned)(v.w * NUM_CLASSES + s.w); if (ix < NBINS) atomicAdd(&sc[ix], 1);
    }
    __syncthreads();
    for (int i = threadIdx.x; i < NBINS; i += blockDim.x)
        if (sc[i]) atomicAdd(&g_counts[i], sc[i]);
}

// ---------------- kernel 2: build LUTs (tiny, 1 thread) ----------------
__global__ void lutK(const int* __restrict__ ids2d, int n2d) {
    bool in2d[MAX_ID + 1];
    for (int i = 0; i <= MAX_ID; i++) in2d[i] = false;
    for (int t = 0; t < n2d; t++) {
        int v = ids2d[t] + 1;
        if (v >= 1 && v <= MAX_ID) in2d[v] = true;
    }
    int hist[MAX_ID + 1];
    for (int i = 0; i <= MAX_ID; i++) {
        int h = 0;
        for (int c = 0; c < NUM_CLASSES; c++) h += g_counts[i * NUM_CLASSES + c];
        hist[i] = h;
    }
    // zero_present: any voxel whose instance id is NOT in ids2d+1
    int zero_present = 0;
    for (int i = 0; i <= MAX_ID; i++)
        if (hist[i] > 0 && !in2d[i]) zero_present = 1;

    bool present[MAX_ID + 1];
    int  pano_ids[MAX_ID + 1];
    int rank = 0;
    g_pano_lut[0] = 0;
    for (int i = 1; i <= MAX_ID; i++) {
        present[i] = in2d[i] && (hist[i] > 0);
        if (present[i]) rank++;
        pano_ids[i] = present[i] ? (rank - 1 + zero_present + 2) : 0;
        g_pano_lut[i] = pano_ids[i];
    }
    // majority semantic label per id (first max wins; cols 0,10,11 = -1)
    int sel_label[MAX_ID + 1];
    for (int i = 1; i <= MAX_ID; i++) {
        int best = -2147483647, bi = 0;
        for (int c = 0; c < NUM_CLASSES; c++) {
            int v = (c == 0 || c == 10 || c == 11) ? -1 : g_counts[i * NUM_CLASSES + c];
            if (v > best) { best = v; bi = c; }
        }
        sel_label[i] = bi;
    }
    // sem_lut: zeros; [1]=wall(10); [2]=floor(11); then pano_ids scatter
    for (int k = 0; k < LUT_SZ; k++) g_sem_lut[k] = 0;
    g_sem_lut[1] = 10;
    g_sem_lut[2] = 11;
    for (int i = 1; i <= MAX_ID; i++) {
        int idx = pano_ids[i];
        int val = present[i] ? sel_label[i] : 0;
        if (idx >= 0 && idx < LUT_SZ) g_sem_lut[idx] = val;
    }
}

// ---------------- kernel 3: grid0 = pano_lut[inst] with wall/floor overrides ----------------
__global__ void grid0K() {
    __shared__ unsigned char lut[MAX_ID + 1];
    if (threadIdx.x <= MAX_ID) lut[threadIdx.x] = (unsigned char)g_pano_lut[threadIdx.x];
    __syncthreads();
    int i = blockIdx.x * blockDim.x + threadIdx.x;
    int n4 = NVOX / 4;
    if (i >= n4) return;
    int4 v = ((const int4*)g_inst)[i];
    int4 s = ((const int4*)g_sem)[i];
    v.x &= 31; v.y &= 31; v.z &= 31; v.w &= 31;
    uchar4 o;
    o.x = (s.x == 10) ? 1 : ((s.x == 11) ? 2 : lut[v.x]);
    o.y = (s.y == 10) ? 1 : ((s.y == 11) ? 2 : lut[v.y]);
    o.z = (s.z == 10) ? 1 : ((s.z == 11) ? 2 : lut[v.z]);
    o.w = (s.w == 10) ? 1 : ((s.w == 11) ? 2 : lut[v.w]);
    ((uchar4*)g_grid0)[i] = o;
}

// ---------------- kernel 4: nn_search + FLOAT32 outputs ----------------
__global__ void nnK(float* __restrict__ out, long long out_elems) {
    __shared__ float slut[LUT_SZ];
    if (threadIdx.x < LUT_SZ) slut[threadIdx.x] = (float)g_sem_lut[threadIdx.x];
    __syncthreads();
    int idx = blockIdx.x * blockDim.x + threadIdx.x;
    if (idx >= NVOX) return;

    int label = g_grid0[idx];
    float g = g_geo[idx];
    if (label == 0 && fabsf(g) <= 1.5f) {
        int k = idx & 255;
        int j = (idx >> 8) & 255;
        int i = idx >> 16;
        // lexicographic offsets di,dj,dk in [-3,3); first positive neighbor wins
        #pragma unroll 1
        for (int di = -3; di < 3 && !label; di++) {
            int ii = (i + di) & 255;
            #pragma unroll 1
            for (int dj = -3; dj < 3 && !label; dj++) {
                int jj = (j + dj) & 255;
                const unsigned char* row = &g_grid0[(ii << 16) | (jj << 8)];
                #pragma unroll
                for (int dk = -3; dk < 3; dk++) {
                    int v = row[(k + dk) & 255];
                    if (v > 0) { label = v; break; }
                }
            }
        }
    }

    // FLOAT stores — output dtype is float32
    if ((long long)idx < out_elems)        out[idx]        = (float)label;
    if ((long long)idx + NVOX < out_elems) out[idx + NVOX] = slut[label];
}

// ---------------- launch ----------------
extern "C" void kernel_launch(void* const* d_in, const int* in_sizes, int n_in,
                              void* d_out, int out_size) {
    const int* big[3] = { 0, 0, 0 };
    const int* ids2d = 0;
    int n2d = 0, nb = 0;
    for (int t = 0; t < n_in; t++) {
        if (in_sizes[t] < 1024) { ids2d = (const int*)d_in[t]; n2d = in_sizes[t]; }
        else if (nb < 3)        { big[nb++] = (const int*)d_in[t]; }
    }

    float* out = (float*)d_out;
    long long out_elems = (long long)out_size;

    classifyK<<<1, 128>>>(big[0], big[1], big[2]);
    histK<<<1024, 256>>>();
    if (ids2d) lutK<<<1, 1>>>(ids2d, n2d);
    grid0K<<<(NVOX / 4 + 255) / 256, 256>>>();
    nnK<<<NVOX / 256, 256>>>(out, out_elems);
}

// round 10
// speedup vs baseline: 1.6386x; 1.6386x over previous
#include <cuda_runtime.h>
#include <math.h>

#define GN 256
#define NVOX (GN*GN*GN)          // 2^24
#define MAX_ID 32
#define NUM_CLASSES 13
#define NBINS ((MAX_ID+1)*NUM_CLASSES)   // 429
#define LUT_SZ (MAX_ID+3)                // 35
#define KEY_WALL  253
#define KEY_FLOOR 254

// ---------------- device scratch (no allocations allowed) ----------------
__device__ int           g_counts[NBINS];
__device__ int           g_pano_lut[MAX_ID+1];
__device__ int           g_sem_lut[LUT_SZ];
__device__ unsigned char g_key[NVOX];     // per-voxel key: 253=wall, 254=floor, else inst
__device__ unsigned char g_grid0[NVOX];   // panoptic label before nn fill

__device__ const float* g_geo;
__device__ const int*   g_inst;
__device__ const int*   g_sem;

// ---------------- kernel A: classify big buffers by content (3 warps) ----------------
__global__ void classifyK(const int* a, const int* b, const int* c) {
    __shared__ int smax[3];
    const int* bufs[3] = { a, b, c };
    int w = threadIdx.x >> 5, lane = threadIdx.x & 31;
    if (w < 3) {
        const int* p = bufs[w];
        int mx = -2147483647;
        for (int i = lane; i < 2048; i += 32) {
            int v = p[i * 769];
            mx = v > mx ? v : mx;
        }
        for (int o = 16; o > 0; o >>= 1) {
            int t = __shfl_xor_sync(0xFFFFFFFFu, mx, o);
            mx = t > mx ? t : mx;
        }
        if (lane == 0) smax[w] = mx;
    }
    __syncthreads();
    if (threadIdx.x == 0) {
        bool used[3] = { false, false, false };
        bool gs = false, ss = false, is = false;
        for (int t = 0; t < 3; t++)
            if (!used[t] && (smax[t] > 1000000 || smax[t] < 0)) {
                g_geo = (const float*)bufs[t]; used[t] = true; gs = true; break;
            }
        for (int t = 0; t < 3; t++)
            if (!used[t] && smax[t] < 13) {
                g_sem = bufs[t]; used[t] = true; ss = true; break;
            }
        for (int t = 0; t < 3; t++)
            if (!used[t]) { g_inst = bufs[t]; used[t] = true; is = true; break; }
        if (!gs) g_geo  = (const float*)a;
        if (!ss) g_sem  = c;
        if (!is) g_inst = b;
    }
    for (int i = threadIdx.x; i < NBINS; i += blockDim.x) g_counts[i] = 0;
}

// ---------------- kernel 1: joint histogram + key-grid emission ----------------
__global__ void histK() {
    __shared__ int sc[NBINS];
    for (int i = threadIdx.x; i < NBINS; i += blockDim.x) sc[i] = 0;
    __syncthreads();

    const int4* inst4 = (const int4*)g_inst;
    const int4* sem4  = (const int4*)g_sem;
    uchar4*     key4  = (uchar4*)g_key;
    int stride = gridDim.x * blockDim.x;
    int n4 = NVOX / 4;
    for (int i = blockIdx.x * blockDim.x + threadIdx.x; i < n4; i += stride) {
        int4 v = inst4[i];
        int4 s = sem4[i];
        unsigned ix;
        ix = (unsigned)(v.x * NUM_CLASSES + s.x); if (ix < NBINS) atomicAdd(&sc[ix], 1);
        ix = (unsigned)(v.y * NUM_CLASSES + s.y); if (ix < NBINS) atomicAdd(&sc[ix], 1);
        ix = (unsigned)(v.z * NUM_CLASSES + s.z); if (ix < NBINS) atomicAdd(&sc[ix], 1);
        ix = (unsigned)(v.w * NUM_CLASSES + s.w); if (ix < NBINS) atomicAdd(&sc[ix], 1);
        uchar4 k;
        k.x = (s.x == 10) ? KEY_WALL : ((s.x == 11) ? KEY_FLOOR : (unsigned char)(v.x & 31));
        k.y = (s.y == 10) ? KEY_WALL : ((s.y == 11) ? KEY_FLOOR : (unsigned char)(v.y & 31));
        k.z = (s.z == 10) ? KEY_WALL : ((s.z == 11) ? KEY_FLOOR : (unsigned char)(v.z & 31));
        k.w = (s.w == 10) ? KEY_WALL : ((s.w == 11) ? KEY_FLOOR : (unsigned char)(v.w & 31));
        key4[i] = k;
    }
    __syncthreads();
    for (int i = threadIdx.x; i < NBINS; i += blockDim.x)
        if (sc[i]) atomicAdd(&g_counts[i], sc[i]);
}

// ---------------- kernel 2: build LUTs (tiny, 1 thread) ----------------
__global__ void lutK(const int* __restrict__ ids2d, int n2d) {
    bool in2d[MAX_ID + 1];
    for (int i = 0; i <= MAX_ID; i++) in2d[i] = false;
    for (int t = 0; t < n2d; t++) {
        int v = ids2d[t] + 1;
        if (v >= 1 && v <= MAX_ID) in2d[v] = true;
    }
    int hist[MAX_ID + 1];
    for (int i = 0; i <= MAX_ID; i++) {
        int h = 0;
        for (int c = 0; c < NUM_CLASSES; c++) h += g_counts[i * NUM_CLASSES + c];
        hist[i] = h;
    }
    int zero_present = 0;
    for (int i = 0; i <= MAX_ID; i++)
        if (hist[i] > 0 && !in2d[i]) zero_present = 1;

    bool present[MAX_ID + 1];
    int  pano_ids[MAX_ID + 1];
    int rank = 0;
    g_pano_lut[0] = 0;
    for (int i = 1; i <= MAX_ID; i++) {
        present[i] = in2d[i] && (hist[i] > 0);
        if (present[i]) rank++;
        pano_ids[i] = present[i] ? (rank - 1 + zero_present + 2) : 0;
        g_pano_lut[i] = pano_ids[i];
    }
    int sel_label[MAX_ID + 1];
    for (int i = 1; i <= MAX_ID; i++) {
        int best = -2147483647, bi = 0;
        for (int c = 0; c < NUM_CLASSES; c++) {
            int v = (c == 0 || c == 10 || c == 11) ? -1 : g_counts[i * NUM_CLASSES + c];
            if (v > best) { best = v; bi = c; }
        }
        sel_label[i] = bi;
    }
    for (int k = 0; k < LUT_SZ; k++) g_sem_lut[k] = 0;
    g_sem_lut[1] = 10;
    g_sem_lut[2] = 11;
    for (int i = 1; i <= MAX_ID; i++) {
        int idx = pano_ids[i];
        int val = present[i] ? sel_label[i] : 0;
        if (idx >= 0 && idx < LUT_SZ) g_sem_lut[idx] = val;
    }
}

// ---------------- kernel 3: grid0 = keyLUT[key] (32 MB traffic) ----------------
__global__ void grid0K() {
    __shared__ unsigned char lut[256];
    {
        int t = threadIdx.x;
        if (t < 256) {
            unsigned char v = 0;
            if (t < 32)            v = (unsigned char)g_pano_lut[t];
            else if (t == KEY_WALL)  v = 1;
            else if (t == KEY_FLOOR) v = 2;
            lut[t] = v;
        }
    }
    __syncthreads();
    int i = blockIdx.x * blockDim.x + threadIdx.x;
    int n4 = NVOX / 4;
    if (i >= n4) return;
    uchar4 k = ((const uchar4*)g_key)[i];
    uchar4 o;
    o.x = lut[k.x]; o.y = lut[k.y]; o.z = lut[k.z]; o.w = lut[k.w];
    ((uchar4*)g_grid0)[i] = o;
}

// ---------------- kernel 4: nn_search + float4 outputs ----------------
__global__ void nnK(float* __restrict__ out, long long out_elems) {
    __shared__ float slut[LUT_SZ];
    if (threadIdx.x < LUT_SZ) slut[threadIdx.x] = (float)g_sem_lut[threadIdx.x];
    __syncthreads();

    int t = blockIdx.x * blockDim.x + threadIdx.x;   // 4 voxels per thread
    int n4 = NVOX / 4;
    if (t >= n4) return;
    int base = t * 4;

    uchar4 l4 = ((const uchar4*)g_grid0)[t];
    float4 g4 = ((const float4*)g_geo)[t];

    int lab[4] = { l4.x, l4.y, l4.z, l4.w };
    float gg[4] = { g4.x, g4.y, g4.z, g4.w };

    #pragma unroll
    for (int q = 0; q < 4; q++) {
        int label = lab[q];
        if (label == 0 && fabsf(gg[q]) <= 1.5f) {
            int idx = base + q;
            int k = idx & 255;
            int j = (idx >> 8) & 255;
            int i = idx >> 16;
            #pragma unroll 1
            for (int di = -3; di < 3 && !label; di++) {
                int ii = (i + di) & 255;
                #pragma unroll 1
                for (int dj = -3; dj < 3 && !label; dj++) {
                    int jj = (j + dj) & 255;
                    const unsigned char* row = &g_grid0[(ii << 16) | (jj << 8)];
                    #pragma unroll
                    for (int dk = -3; dk < 3; dk++) {
                        int v = row[(k + dk) & 255];
                        if (v > 0) { label = v; break; }
                    }
                }
            }
            lab[q] = label;
        }
    }

    float4 po = make_float4((float)lab[0], (float)lab[1], (float)lab[2], (float)lab[3]);
    float4 so = make_float4(slut[lab[0]], slut[lab[1]], slut[lab[2]], slut[lab[3]]);

    if ((long long)base + 3 < out_elems)
        ((float4*)out)[t] = po;
    if ((long long)base + NVOX + 3 < out_elems)
        ((float4*)(out + NVOX))[t] = so;
}

// ---------------- launch ----------------
extern "C" void kernel_launch(void* const* d_in, const int* in_sizes, int n_in,
                              void* d_out, int out_size) {
    const int* big[3] = { 0, 0, 0 };
    const int* ids2d = 0;
    int n2d = 0, nb = 0;
    for (int t = 0; t < n_in; t++) {
        if (in_sizes[t] < 1024) { ids2d = (const int*)d_in[t]; n2d = in_sizes[t]; }
        else if (nb < 3)        { big[nb++] = (const int*)d_in[t]; }
    }

    float* out = (float*)d_out;
    long long out_elems = (long long)out_size;

    classifyK<<<1, 128>>>(big[0], big[1], big[2]);
    histK<<<1024, 256>>>();
    if (ids2d) lutK<<<1, 1>>>(ids2d, n2d);
    grid0K<<<(NVOX / 4 + 255) / 256, 256>>>();
    nnK<<<(NVOX / 4 + 255) / 256, 256>>>(out, out_elems);
}